// round 8
// baseline (speedup 1.0000x reference)
#include <cuda_runtime.h>

#define BB  4
#define CHN 128
#define HH  128
#define WW  128
#define HW  16384
#define K2C 1152
#define NPX (BB*HW)

// ---------------- scratch (device globals; allocation-free) ----------------
__device__ float g_xT   [(size_t)NPX*CHN];     // x in NHWC
__device__ float g_xattT[(size_t)NPX*CHN];     // x_attned in NHWC
__device__ float g_attn [(size_t)BB*CHN*HW];   // sigmoid(conv_attn), NCHW
__device__ float g_feat [(size_t)BB*CHN*HW];   // raw conv_feat, NCHW
__device__ float g_xatt [(size_t)BB*CHN*HW];   // x_attned, NCHW
__device__ float g_off  [(size_t)BB*27*HW];    // 18 offsets + 9 sigmoided masks
__device__ float g_dconv[(size_t)BB*CHN*HW];   // deform conv output
// fragment-swizzled weights: [c36][ks4][half][mt4][lane32][e4]
__device__ float g_wAs[36*4*4*4*32*4];         // attn+feat, 4 co-halves of 64
__device__ float g_wts[36*4*2*4*32*4];         // w_org, 2 co-halves of 64
__device__ float g_wM [K2C*32];                // [k][co] off/mask (plain)
__device__ float g_biasA[256];
__device__ float g_biasM[32];
__device__ float g_biasO[128];
__device__ float g_stats[2*BB*CHN*2];
__device__ float g_norm [2*BB*CHN*2];

__device__ __forceinline__ float sigmoidf(float v) { return 1.0f/(1.0f + __expf(-v)); }

__device__ __forceinline__ void mma_tf32(float* d, const unsigned* a,
                                         unsigned b0, unsigned b1) {
    asm volatile(
        "mma.sync.aligned.m16n8k8.row.col.f32.tf32.tf32.f32 "
        "{%0,%1,%2,%3},{%4,%5,%6,%7},{%8,%9},{%0,%1,%2,%3};\n"
        : "+f"(d[0]), "+f"(d[1]), "+f"(d[2]), "+f"(d[3])
        : "r"(a[0]), "r"(a[1]), "r"(a[2]), "r"(a[3]), "r"(b0), "r"(b1));
}

__device__ __forceinline__ void cp16(unsigned dst, const void* src, int srcsize) {
    asm volatile("cp.async.cg.shared.global [%0], [%1], 16, %2;\n"
                 :: "r"(dst), "l"(src), "r"(srcsize));
}
__device__ __forceinline__ void cp_commit() { asm volatile("cp.async.commit_group;\n"); }
__device__ __forceinline__ void cp_wait0()  { asm volatile("cp.async.wait_group 0;\n"); }
__device__ __forceinline__ void cp_wait1()  { asm volatile("cp.async.wait_group 1;\n"); }

// ---------------- prep: repack weights/biases, zero stats ----------------
__global__ void prep_k(const float* __restrict__ w_attn, const float* __restrict__ w_feat,
                       const float* __restrict__ w_org,  const float* __restrict__ w_off,
                       const float* __restrict__ w_mask,
                       const float* __restrict__ b_attn, const float* __restrict__ b_feat,
                       const float* __restrict__ b_org,  const float* __restrict__ b_off,
                       const float* __restrict__ b_mask)
{
    int i = blockIdx.x*256 + threadIdx.x;       // 0 .. 294911
    // g_wAs: [c][ks][half4][mt][lane][e]
    {
        int e=i&3, lane=(i>>2)&31, mt=(i>>7)&3, half=(i>>9)&3, ks=(i>>11)&3, c=i>>13;
        int g=lane>>2, tig=lane&3;
        int k  = c*32 + ks*8 + tig + ((e>>1) ? 4 : 0);
        int co = half*64 + mt*16 + g + ((e&1) ? 8 : 0);
        int tap = k>>7, ci = k&127;
        g_wAs[i] = (co < 128) ? w_attn[(co*128+ci)*9 + tap]
                              : w_feat[((co-128)*128+ci)*9 + tap];
    }
    // g_wts: [c][ks][half2][mt][lane][e]
    if (i < 36*4*2*4*32*4) {
        int e=i&3, lane=(i>>2)&31, mt=(i>>7)&3, half=(i>>9)&1, ks=(i>>10)&3, c=i>>12;
        int g=lane>>2, tig=lane&3;
        int k  = c*32 + ks*8 + tig + ((e>>1) ? 4 : 0);
        int co = half*64 + mt*16 + g + ((e&1) ? 8 : 0);
        int tap = k>>7, ci = k&127;
        g_wts[i] = w_org[(co*128+ci)*9 + tap];
    }
    if (i < K2C*32) {
        int k = i >> 5, co = i & 31;
        int tap = k >> 7, ci = k & 127;
        float v = 0.f;
        if (co < 18)      v = w_off [(co*128+ci)*9 + tap];
        else if (co < 27) v = w_mask[((co-18)*128+ci)*9 + tap];
        g_wM[i] = v;
    }
    if (i < 256) g_biasA[i] = (i < 128) ? b_attn[i] : b_feat[i-128];
    if (i < 128) g_biasO[i] = b_org[i];
    if (i < 32)  g_biasM[i] = (i < 18) ? b_off[i] : (i < 27 ? b_mask[i-18] : 0.f);
    if (i < 2*BB*CHN*2) g_stats[i] = 0.f;
}

// ---------------- NCHW -> NHWC transpose of x (smem-tiled) ----------------
__global__ __launch_bounds__(256) void transpose_k(const float* __restrict__ x) {
    __shared__ float s[32][133];
    int bid = blockIdx.x;
    int pg = bid & 127, cg = (bid >> 7) & 3, b = bid >> 9;
    int t = threadIdx.x;
    int px0 = pg << 7;
    #pragma unroll
    for (int j = 0; j < 16; j++) {
        int idx = t + j*256;
        int ch = idx >> 7, px = idx & 127;
        s[ch][px] = x[((size_t)(b*CHN + (cg<<5) + ch) << 14) + px0 + px];
    }
    __syncthreads();
    #pragma unroll
    for (int j = 0; j < 16; j++) {
        int idx = t + j*256;
        int px = idx >> 5, ch = idx & 31;
        g_xT[((size_t)((b<<14) + px0 + px))*CHN + (cg<<5) + ch] = s[ch][px];
    }
}

// ---------------- generic TF32 GEMM with implicit im2col / gather ----------
// MODE 0: attn+feat conv (3-stage); MODE 1: off/mask conv (3-stage);
// MODE 2: fused deform gather + einsum (2-stage, register-pipelined gather)
template<int MODE>
__global__ __launch_bounds__(256, 2) void gemm_k()
{
    constexpr int MT     = (MODE==1) ? 2 : 4;
    constexpr int NT     = (MODE==1) ? 2 : 4;
    constexpr int A_BUF  = (MODE==1) ? 32*40 : 4096;
    constexpr int B_BUF  = 128*36;
    constexpr int STAGES = (MODE==2) ? 2 : 3;
    extern __shared__ float sm[];
    float* as  = sm;                       // [STAGES][A_BUF]
    float* bsm = sm + STAGES*A_BUF;        // [STAGES][128][36]
    float* cwT = bsm + STAGES*B_BUF;       // MODE2: float4[1152] corner weights
    int*   ciT = (int*)(cwT + 4608);       // MODE2: int4[1152] corner indices

    const int t = threadIdx.x;
    const int wid = t >> 5, lane = t & 31, g = lane >> 2, tig = lane & 3;
    const int px0 = blockIdx.x << 7;
    const int bI = px0 >> 14, y = (px0 >> 7) & 127;
    const int yblk = (MODE==0) ? blockIdx.y : 0;
    const int co0 = yblk << 7;
    const int half = (MODE==1) ? 0 : (wid >> 2);
    const int cow  = half * 64;
    const int pxw  = (MODE==1) ? (wid << 4) : ((wid & 3) << 5);

    float acc[MT][NT][4];
    #pragma unroll
    for (int mt = 0; mt < MT; mt++)
        #pragma unroll
        for (int nt = 0; nt < NT; nt++)
            #pragma unroll
            for (int j = 0; j < 4; j++) acc[mt][nt][j] = 0.f;

    const int bpx = t & 127, kq0 = t >> 7;

    // ---- MODE 2: precompute bilinear corner tables (128 px x 9 taps) ----
    if (MODE == 2) {
        const float* ob = g_off + (((size_t)bI*27) << 14) + y*WW;
        for (int pt = t; pt < 1152; pt += 256) {
            int tap = pt >> 7, px = pt & 127;
            float dy = ob[((size_t)(2*tap  ) << 14) + px];
            float dx = ob[((size_t)(2*tap+1) << 14) + px];
            float mk = ob[((size_t)(18+tap ) << 14) + px];
            float yy = dy + (float)(y  + tap/3 - 1);
            float xx = dx + (float)(px + tap%3 - 1);
            float y0f = floorf(yy), x0f = floorf(xx);
            float wy = yy - y0f, wx = xx - x0f;
            int y0 = (int)y0f, x0 = (int)x0f;
            float fw[4]; int fi[4];
            #pragma unroll
            for (int cnr = 0; cnr < 4; cnr++) {
                int ddy = cnr >> 1, ddx = cnr & 1;
                int yi = y0 + ddy, xi = x0 + ddx;
                bool valid = ((unsigned)yi < (unsigned)HH) && ((unsigned)xi < (unsigned)WW);
                int yc = min(max(yi, 0), HH-1);
                int xc = min(max(xi, 0), WW-1);
                float wgt = (ddy ? wy : 1.f - wy) * (ddx ? wx : 1.f - wx) * mk;
                fw[cnr] = valid ? wgt : 0.f;
                fi[cnr] = yc*WW + xc;
            }
            ((float4*)cwT)[pt] = make_float4(fw[0], fw[1], fw[2], fw[3]);
            ((int4*)ciT)[pt]   = make_int4(fi[0], fi[1], fi[2], fi[3]);
        }
        __syncthreads();
    }

    // ---- staging helper (caller commits) ----
    auto stage = [&](int c, int buf) {
        if (MODE == 1) {
            int arow = t >> 3, aco = (t & 7) << 2;
            unsigned d = (unsigned)__cvta_generic_to_shared(as + buf*A_BUF + arow*40 + aco);
            cp16(d, g_wM + (size_t)(c*32 + arow)*32 + aco, 16);
        } else if (MODE == 0) {
            #pragma unroll
            for (int j = 0; j < 4; j++) {
                int i = t + j*256;   // 1024 float4s
                unsigned d = (unsigned)__cvta_generic_to_shared(as + buf*A_BUF + i*4);
                const float* src = g_wAs + ((size_t)c*2048 + (size_t)(i>>8)*512
                                            + (size_t)yblk*256 + (i & 255)) * 4;
                cp16(d, src, 16);
            }
        } else {
            #pragma unroll
            for (int j = 0; j < 4; j++) {
                int i = t + j*256;
                unsigned d = (unsigned)__cvta_generic_to_shared(as + buf*A_BUF + i*4);
                const float* src = g_wts + ((size_t)c*1024 + i) * 4;
                cp16(d, src, 16);
            }
        }
        if (MODE != 2) {
            const float* srcT = (MODE==0) ? g_xT : g_xattT;
            int tap = c >> 2, ci0 = (c & 3) << 5;
            int dy = tap/3 - 1, dxx = tap - (tap/3)*3 - 1;
            int yp = y + dy, xp = bpx + dxx;
            bool valid = ((unsigned)yp < 128u) && ((unsigned)xp < 128u);
            int sz = valid ? 16 : 0;
            const float* src = srcT + ((size_t)((bI<<14) + (valid ? (yp<<7)+xp : 0)))*CHN + ci0;
            #pragma unroll
            for (int j = 0; j < 4; j++) {
                int kq = kq0 + j*2;
                unsigned d = (unsigned)__cvta_generic_to_shared(bsm + buf*B_BUF + bpx*36 + kq*4);
                cp16(d, src + kq*4, sz);
            }
        }
    };

    // ==================== MODE 0 / 1: 3-stage pipeline ====================
    if (MODE != 2) {
        stage(0, 0); cp_commit();
        stage(1, 1); cp_commit();
        for (int c = 0; c < 36; c++) {
            if (c < 35) cp_wait1(); else cp_wait0();
            __syncthreads();
            if (c + 2 < 36) { stage(c+2, (c+2)%3); cp_commit(); }
            const float* __restrict__ ab = as  + (c%3)*A_BUF;
            const float* __restrict__ bb = bsm + (c%3)*B_BUF;
            #pragma unroll
            for (int ks = 0; ks < 4; ks++) {
                unsigned a[MT][4];
                if (MODE == 1) {
                    const float* ar = ab + (ks*8 + tig)*40 + g;
                    #pragma unroll
                    for (int mt = 0; mt < MT; mt++) {
                        a[mt][0] = __float_as_uint(ar[mt*16]);
                        a[mt][1] = __float_as_uint(ar[mt*16 + 8]);
                        a[mt][2] = __float_as_uint(ar[mt*16 + 4*40]);
                        a[mt][3] = __float_as_uint(ar[mt*16 + 4*40 + 8]);
                    }
                } else {
                    const float4* ap4 = ((const float4*)ab) + (ks*2 + half)*128 + lane;
                    #pragma unroll
                    for (int mt = 0; mt < MT; mt++) {
                        float4 av = ap4[mt*32];
                        a[mt][0] = __float_as_uint(av.x);
                        a[mt][1] = __float_as_uint(av.y);
                        a[mt][2] = __float_as_uint(av.z);
                        a[mt][3] = __float_as_uint(av.w);
                    }
                }
                #pragma unroll
                for (int nt = 0; nt < NT; nt++) {
                    const float* bp = bb + (pxw + nt*8 + g)*36 + ks*8 + tig;
                    unsigned b0 = __float_as_uint(bp[0]);
                    unsigned b1 = __float_as_uint(bp[4]);
                    #pragma unroll
                    for (int mt = 0; mt < MT; mt++)
                        mma_tf32(acc[mt][nt], a[mt], b0, b1);
                }
            }
            // barrier at top of next iteration protects buffer reuse
        }
    }
    // ==================== MODE 2: 2-stage + register-pipelined gather ======
    else {
        stage(0, 0); cp_commit();
        {   // gather chunk 0 directly (tap 0, ci 0..31)
            const float* xb = g_xattT + ((size_t)(bI << 14))*CHN + lane;
            const float4* fw0 = (const float4*)cwT;
            const int4*   iw0 = (const int4*)ciT;
            float* bd = bsm + lane;
            #pragma unroll 4
            for (int idx = 0; idx < 16; idx++) {
                int px = wid + idx*8;
                float4 f = fw0[px]; int4 ix = iw0[px];
                bd[px*36] = f.x*xb[(size_t)ix.x*CHN] + f.y*xb[(size_t)ix.y*CHN]
                          + f.z*xb[(size_t)ix.z*CHN] + f.w*xb[(size_t)ix.w*CHN];
            }
        }
        cp_wait0(); __syncthreads();

        for (int c = 0; c < 36; c++) {
            const int buf = c & 1;
            if (c < 35) { stage(c+1, buf^1); cp_commit(); }

            const float* xb = nullptr; const float4* fw = nullptr;
            const int4* iwp = nullptr; float* bdst = nullptr;
            if (c < 35) {
                int cn = c + 1, tapn = cn >> 2, ci0n = (cn & 3) << 5;
                xb   = g_xattT + ((size_t)(bI << 14))*CHN + ci0n + lane;
                fw   = ((const float4*)cwT) + tapn*128;
                iwp  = ((const int4*)ciT)  + tapn*128;
                bdst = bsm + (buf^1)*B_BUF + lane;
            }

            const float* __restrict__ ab = as  + buf*A_BUF;
            const float* __restrict__ bb = bsm + buf*B_BUF;
            #pragma unroll
            for (int ks = 0; ks < 4; ks++) {
                float lv[16]; int pxa[4];
                if (c < 35) {
                    #pragma unroll
                    for (int q = 0; q < 4; q++) {
                        int px = wid + (ks*4 + q)*8;
                        pxa[q] = px;
                        int4 ix = iwp[px];
                        lv[q*4+0] = xb[(size_t)ix.x*CHN];
                        lv[q*4+1] = xb[(size_t)ix.y*CHN];
                        lv[q*4+2] = xb[(size_t)ix.z*CHN];
                        lv[q*4+3] = xb[(size_t)ix.w*CHN];
                    }
                }
                unsigned a[MT][4];
                const float4* ap4 = ((const float4*)ab) + (ks*2 + half)*128 + lane;
                #pragma unroll
                for (int mt = 0; mt < MT; mt++) {
                    float4 av = ap4[mt*32];
                    a[mt][0] = __float_as_uint(av.x);
                    a[mt][1] = __float_as_uint(av.y);
                    a[mt][2] = __float_as_uint(av.z);
                    a[mt][3] = __float_as_uint(av.w);
                }
                #pragma unroll
                for (int nt = 0; nt < NT; nt++) {
                    const float* bp = bb + (pxw + nt*8 + g)*36 + ks*8 + tig;
                    unsigned b0 = __float_as_uint(bp[0]);
                    unsigned b1 = __float_as_uint(bp[4]);
                    #pragma unroll
                    for (int mt = 0; mt < MT; mt++)
                        mma_tf32(acc[mt][nt], a[mt], b0, b1);
                }
                if (c < 35) {
                    #pragma unroll
                    for (int q = 0; q < 4; q++) {
                        float4 f = fw[pxa[q]];
                        bdst[pxa[q]*36] = f.x*lv[q*4]   + f.y*lv[q*4+1]
                                        + f.z*lv[q*4+2] + f.w*lv[q*4+3];
                    }
                }
            }
            if (c < 35) { cp_wait0(); __syncthreads(); }
        }
    }

    // ---- epilogue ----
    const int prem = px0 & (HW-1);
    #pragma unroll
    for (int mt = 0; mt < MT; mt++) {
        #pragma unroll
        for (int r = 0; r < 2; r++) {
            const int coL = cow + mt*16 + r*8 + g;
            const int coG = co0 + coL;
            float bv = 0.f; float* plane = nullptr;
            bool sig = false, dostats = false; int sidx = 0;
            if (MODE == 0) {
                bv = g_biasA[coG];
                if (coG < 128) { plane = g_attn + ((size_t)(bI*CHN + coG) << 14); sig = true; }
                else {
                    plane = g_feat + ((size_t)(bI*CHN + coG - 128) << 14);
                    dostats = true; sidx = (bI*CHN + coG - 128)*2;
                }
            } else if (MODE == 2) {
                bv = g_biasO[coG];
                plane = g_dconv + ((size_t)(bI*CHN + coG) << 14);
                dostats = true; sidx = (BB*CHN + bI*CHN + coG)*2;
            } else {
                bv = g_biasM[coG];
                if (coG < 27) { plane = g_off + ((size_t)(bI*27 + coG) << 14); sig = (coG >= 18); }
            }
            float s = 0.f, q = 0.f;
            #pragma unroll
            for (int nt = 0; nt < NT; nt++) {
                float v0 = acc[mt][nt][r*2]   + bv;
                float v1 = acc[mt][nt][r*2+1] + bv;
                if (sig) { v0 = sigmoidf(v0); v1 = sigmoidf(v1); }
                int col = pxw + nt*8 + 2*tig;
                if (plane) *(float2*)&plane[prem + col] = make_float2(v0, v1);
                s += v0 + v1; q += v0*v0 + v1*v1;
            }
            if (dostats) {
                s += __shfl_xor_sync(0xffffffffu, s, 1);
                s += __shfl_xor_sync(0xffffffffu, s, 2);
                q += __shfl_xor_sync(0xffffffffu, q, 1);
                q += __shfl_xor_sync(0xffffffffu, q, 2);
                if (tig == 0) {
                    atomicAdd(&g_stats[sidx],   s);
                    atomicAdd(&g_stats[sidx+1], q);
                }
            }
        }
    }
}

__global__ void finalize_stats_k() {
    int i = blockIdx.x*blockDim.x + threadIdx.x;
    if (i >= 2*BB*CHN) return;
    float s = g_stats[2*i], q = g_stats[2*i+1];
    float mu  = s * (1.0f/HW);
    float var = q * (1.0f/HW) - mu*mu;
    g_norm[2*i]   = mu;
    g_norm[2*i+1] = rsqrtf(var + 1e-5f);
}

// ---- x_attned = lrelu(IN(feat)) * attn ; NCHW + NHWC (smem-tiled) ----
__global__ __launch_bounds__(256) void xatt_k() {
    __shared__ float s[32][133];
    int bid = blockIdx.x;
    int pg = bid & 127, cg = (bid >> 7) & 3, b = bid >> 9;
    int t = threadIdx.x;
    int px0 = pg << 7;
    #pragma unroll
    for (int j = 0; j < 16; j++) {
        int idx = t + j*256;
        int ch = idx >> 7, px = idx & 127;
        int plane = b*CHN + (cg<<5) + ch;
        size_t gi = ((size_t)plane << 14) + px0 + px;
        float mu = g_norm[2*plane], rs = g_norm[2*plane+1];
        float v = (g_feat[gi] - mu)*rs;
        v = v > 0.f ? v : 0.2f*v;
        float o = v * g_attn[gi];
        g_xatt[gi] = o;
        s[ch][px] = o;
    }
    __syncthreads();
    #pragma unroll
    for (int j = 0; j < 16; j++) {
        int idx = t + j*256;
        int px = idx >> 5, ch = idx & 31;
        g_xattT[((size_t)((b<<14) + px0 + px))*CHN + (cg<<5) + ch] = s[ch][px];
    }
}

// ---- final: out = xatt + lrelu(IN(dconv)) * (1 - attn) ----
__global__ void final_k(float* __restrict__ out) {
    int i = blockIdx.x*256 + threadIdx.x;
    int plane = i >> 12;
    float mu = g_norm[2*(BB*CHN + plane)], rs = g_norm[2*(BB*CHN + plane)+1];
    float4 d  = ((const float4*)g_dconv)[i];
    float4 a  = ((const float4*)g_attn)[i];
    float4 xa = ((const float4*)g_xatt)[i];
    float4 o; float v;
    v = (d.x - mu)*rs; v = v > 0.f ? v : 0.2f*v; o.x = xa.x + v*(1.f - a.x);
    v = (d.y - mu)*rs; v = v > 0.f ? v : 0.2f*v; o.y = xa.y + v*(1.f - a.y);
    v = (d.z - mu)*rs; v = v > 0.f ? v : 0.2f*v; o.z = xa.z + v*(1.f - a.z);
    v = (d.w - mu)*rs; v = v > 0.f ? v : 0.2f*v; o.w = xa.w + v*(1.f - a.w);
    ((float4*)out)[i] = o;
}

// ---------------- launch ----------------
extern "C" void kernel_launch(void* const* d_in, const int* in_sizes, int n_in,
                              void* d_out, int out_size) {
    const float* x      = (const float*)d_in[0];
    const float* w_attn = (const float*)d_in[1];
    const float* b_attn = (const float*)d_in[2];
    const float* w_feat = (const float*)d_in[3];
    const float* b_feat = (const float*)d_in[4];
    const float* w_org  = (const float*)d_in[5];
    const float* b_org  = (const float*)d_in[6];
    const float* w_off  = (const float*)d_in[7];
    const float* b_off  = (const float*)d_in[8];
    const float* w_mask = (const float*)d_in[9];
    const float* b_mask = (const float*)d_in[10];
    float* out = (float*)d_out;

    const int SM_M0 = 3*(4096 + 4608)*4;                        // 104448
    const int SM_M1 = 3*(32*40 + 4608)*4;                       // 70656
    const int SM_M2 = (2*4096 + 2*4608 + 4608 + 4608)*4;        // 106496
    cudaFuncSetAttribute(gemm_k<0>, cudaFuncAttributeMaxDynamicSharedMemorySize, SM_M0);
    cudaFuncSetAttribute(gemm_k<1>, cudaFuncAttributeMaxDynamicSharedMemorySize, SM_M1);
    cudaFuncSetAttribute(gemm_k<2>, cudaFuncAttributeMaxDynamicSharedMemorySize, SM_M2);

    prep_k<<<1152, 256>>>(w_attn, w_feat, w_org, w_off, w_mask,
                          b_attn, b_feat, b_org, b_off, b_mask);
    transpose_k<<<2048, 256>>>(x);
    gemm_k<0><<<dim3(512, 2), 256, SM_M0>>>();     // attn + feat conv
    finalize_stats_k<<<4, 256>>>();
    xatt_k<<<2048, 256>>>();
    gemm_k<1><<<dim3(512, 1), 256, SM_M1>>>();     // offset + mask conv
    gemm_k<2><<<dim3(512, 1), 256, SM_M2>>>();     // fused gather + deform einsum
    finalize_stats_k<<<4, 256>>>();
    final_k<<<8192, 256>>>(out);
}

// round 10
// speedup vs baseline: 1.3848x; 1.3848x over previous
#include <cuda_runtime.h>
#include <cuda_fp16.h>
#include <cstdint>

#define BB  4
#define CHN 128
#define HH  128
#define WW  128
#define HW  16384
#define K2C 1152
#define NPX (BB*HW)

// ---------------- scratch (device globals; allocation-free) ----------------
__device__ __half g_xTh   [(size_t)NPX*CHN];   // x in NHWC, fp16
__device__ __half g_xattTh[(size_t)NPX*CHN];   // x_attned in NHWC, fp16
__device__ float g_attn [(size_t)BB*CHN*HW];   // sigmoid(conv_attn), NCHW
__device__ float g_feat [(size_t)BB*CHN*HW];   // raw conv_feat, NCHW
__device__ float g_xatt [(size_t)BB*CHN*HW];   // x_attned, NCHW
__device__ float g_off  [(size_t)BB*27*HW];    // 18 offsets + 9 sigmoided masks
__device__ float g_dconv[(size_t)BB*CHN*HW];   // deform conv output
// fp16 fragment-packed weights (m16n8k16 layout)
__device__ __half g_wAh[36*2*4*4*32*8];        // [c][ks2][halfb4][mt4][lane][8] attn+feat
__device__ __half g_wth[36*2*2*4*32*8];        // [c][ks2][halfb2][mt4][lane][8] w_org
__device__ __half g_wMh[36*2*2*32*8];          // [c][ks2][mt2][lane][8]        off/mask
__device__ float g_biasA[256];
__device__ float g_biasM[32];
__device__ float g_biasO[128];
__device__ float g_stats[2*BB*CHN*2];
__device__ float g_norm [2*BB*CHN*2];

__device__ __forceinline__ float sigmoidf(float v) { return 1.0f/(1.0f + __expf(-v)); }

__device__ __forceinline__ void mma_f16(float* d, const uint32_t* a,
                                        uint32_t b0, uint32_t b1) {
    asm volatile(
        "mma.sync.aligned.m16n8k16.row.col.f32.f16.f16.f32 "
        "{%0,%1,%2,%3},{%4,%5,%6,%7},{%8,%9},{%0,%1,%2,%3};\n"
        : "+f"(d[0]), "+f"(d[1]), "+f"(d[2]), "+f"(d[3])
        : "r"(a[0]), "r"(a[1]), "r"(a[2]), "r"(a[3]), "r"(b0), "r"(b1));
}

__device__ __forceinline__ void cp16(unsigned dst, const void* src, int srcsize) {
    asm volatile("cp.async.cg.shared.global [%0], [%1], 16, %2;\n"
                 :: "r"(dst), "l"(src), "r"(srcsize));
}
__device__ __forceinline__ void cp_commit() { asm volatile("cp.async.commit_group;\n"); }
__device__ __forceinline__ void cp_wait0()  { asm volatile("cp.async.wait_group 0;\n"); }
__device__ __forceinline__ void cp_wait1()  { asm volatile("cp.async.wait_group 1;\n"); }

// ---------------- prep: pack weights into fp16 fragments ----------------
// fragment element mapping (m16n8k16, A row-major co x k):
//   e = reg*2 + h;  co += (reg&1)?8:0;  k += tig*2 + h + ((reg&2)?8:0)
__global__ void prep_k(const float* __restrict__ w_attn, const float* __restrict__ w_feat,
                       const float* __restrict__ w_org,  const float* __restrict__ w_off,
                       const float* __restrict__ w_mask,
                       const float* __restrict__ b_attn, const float* __restrict__ b_feat,
                       const float* __restrict__ b_org,  const float* __restrict__ b_off,
                       const float* __restrict__ b_mask)
{
    int i = blockIdx.x*256 + threadIdx.x;       // 0 .. 294911
    {   // g_wAh
        int e = i & 7, lane = (i>>3) & 31, mt = (i>>8) & 3,
            hb = (i>>10) & 3, ks = (i>>12) & 1, c = i >> 13;
        int g = lane>>2, tig = lane&3, r = e>>1, h = e&1;
        int co = hb*64 + mt*16 + g + ((r&1) ? 8 : 0);
        int k  = c*32 + ks*16 + tig*2 + h + ((r&2) ? 8 : 0);
        int tap = k >> 7, ci = k & 127;
        float v = (co < 128) ? w_attn[(co*128+ci)*9 + tap]
                             : w_feat[((co-128)*128+ci)*9 + tap];
        g_wAh[i] = __float2half(v);
    }
    if (i < 36*2*2*4*32*8) {   // g_wth
        int e = i & 7, lane = (i>>3) & 31, mt = (i>>8) & 3,
            hb = (i>>10) & 1, ks = (i>>11) & 1, c = i >> 12;
        int g = lane>>2, tig = lane&3, r = e>>1, h = e&1;
        int co = hb*64 + mt*16 + g + ((r&1) ? 8 : 0);
        int k  = c*32 + ks*16 + tig*2 + h + ((r&2) ? 8 : 0);
        int tap = k >> 7, ci = k & 127;
        g_wth[i] = __float2half(w_org[(co*128+ci)*9 + tap]);
    }
    if (i < 36*2*2*32*8) {     // g_wMh
        int e = i & 7, lane = (i>>3) & 31, mt = (i>>8) & 1,
            ks = (i>>9) & 1, c = i >> 10;
        int g = lane>>2, tig = lane&3, r = e>>1, h = e&1;
        int co = mt*16 + g + ((r&1) ? 8 : 0);
        int k  = c*32 + ks*16 + tig*2 + h + ((r&2) ? 8 : 0);
        int tap = k >> 7, ci = k & 127;
        float v = 0.f;
        if (co < 18)      v = w_off [(co*128+ci)*9 + tap];
        else if (co < 27) v = w_mask[((co-18)*128+ci)*9 + tap];
        g_wMh[i] = __float2half(v);
    }
    if (i < 256) g_biasA[i] = (i < 128) ? b_attn[i] : b_feat[i-128];
    if (i < 128) g_biasO[i] = b_org[i];
    if (i < 32)  g_biasM[i] = (i < 18) ? b_off[i] : (i < 27 ? b_mask[i-18] : 0.f);
    if (i < 2*BB*CHN*2) g_stats[i] = 0.f;
}

// ---------------- NCHW -> NHWC(fp16) transpose of x ----------------
__global__ __launch_bounds__(256) void transpose_k(const float* __restrict__ x) {
    __shared__ float s[32][133];
    int bid = blockIdx.x;
    int pg = bid & 127, cg = (bid >> 7) & 3, b = bid >> 9;
    int t = threadIdx.x;
    int px0 = pg << 7;
    #pragma unroll
    for (int j = 0; j < 16; j++) {
        int idx = t + j*256;
        int ch = idx >> 7, px = idx & 127;
        s[ch][px] = x[((size_t)(b*CHN + (cg<<5) + ch) << 14) + px0 + px];
    }
    __syncthreads();
    #pragma unroll
    for (int j = 0; j < 16; j++) {
        int idx = t + j*256;
        int px = idx >> 5, ch = idx & 31;
        g_xTh[((size_t)((b<<14) + px0 + px))*CHN + (cg<<5) + ch] = __float2half(s[ch][px]);
    }
}

// ---------------- generic fp16 GEMM with implicit im2col / gather ----------
// MODE 0: attn+feat conv; MODE 1: off/mask conv; MODE 2: fused deform einsum
template<int MODE>
__global__ __launch_bounds__(256, 2) void gemm_k()
{
    constexpr int MT     = (MODE==1) ? 2 : 4;
    constexpr int NT     = (MODE==1) ? 2 : 4;
    constexpr int NH     = (MODE==1) ? 1 : 2;
    constexpr int A_H    = (MODE==1) ? 1024 : 4096;   // halves per stage
    constexpr int B_H    = 128*40;                    // 5120 halves per stage
    constexpr int STAGES = (MODE==2) ? 2 : 3;
    extern __shared__ __half smh[];
    __half* as  = smh;
    __half* bsm = smh + STAGES*A_H;
    float*  cwT = (float*)(smh + STAGES*(A_H + B_H));  // MODE2 only
    int*    ciT = (int*)(cwT + 4608);

    const int t = threadIdx.x;
    const int wid = t >> 5, lane = t & 31, g = lane >> 2, tig = lane & 3;
    const int px0 = blockIdx.x << 7;
    const int bI = px0 >> 14, y = (px0 >> 7) & 127;
    const int yblk = (MODE==0) ? blockIdx.y : 0;
    const int co0 = yblk << 7;
    const int halfsel = (MODE==1) ? 0 : (wid >> 2);
    const int cow = halfsel * 64;
    const int pxw = (MODE==1) ? (wid << 4) : ((wid & 3) << 5);

    float acc[MT][NT][4];
    #pragma unroll
    for (int mt = 0; mt < MT; mt++)
        #pragma unroll
        for (int nt = 0; nt < NT; nt++)
            #pragma unroll
            for (int j = 0; j < 4; j++) acc[mt][nt][j] = 0.f;

    const int bpx = t & 127, kq0 = t >> 7;

    // ---- MODE 2: precompute bilinear corner tables ----
    if (MODE == 2) {
        const float* ob = g_off + (((size_t)bI*27) << 14) + y*WW;
        for (int pt = t; pt < 1152; pt += 256) {
            int tap = pt >> 7, px = pt & 127;
            float dy = ob[((size_t)(2*tap  ) << 14) + px];
            float dx = ob[((size_t)(2*tap+1) << 14) + px];
            float mk = ob[((size_t)(18+tap ) << 14) + px];
            float yy = dy + (float)(y  + tap/3 - 1);
            float xx = dx + (float)(px + tap%3 - 1);
            float y0f = floorf(yy), x0f = floorf(xx);
            float wy = yy - y0f, wx = xx - x0f;
            int y0 = (int)y0f, x0 = (int)x0f;
            float fw[4]; int fi[4];
            #pragma unroll
            for (int cnr = 0; cnr < 4; cnr++) {
                int ddy = cnr >> 1, ddx = cnr & 1;
                int yi = y0 + ddy, xi = x0 + ddx;
                bool valid = ((unsigned)yi < (unsigned)HH) && ((unsigned)xi < (unsigned)WW);
                int yc = min(max(yi, 0), HH-1);
                int xc = min(max(xi, 0), WW-1);
                float wgt = (ddy ? wy : 1.f - wy) * (ddx ? wx : 1.f - wx) * mk;
                fw[cnr] = valid ? wgt : 0.f;
                fi[cnr] = yc*WW + xc;
            }
            ((float4*)cwT)[pt] = make_float4(fw[0], fw[1], fw[2], fw[3]);
            ((int4*)ciT)[pt]   = make_int4(fi[0], fi[1], fi[2], fi[3]);
        }
        __syncthreads();
    }

    // ---- staging helper (caller commits) ----
    auto stage = [&](int c, int buf) {
        if (MODE == 0) {
            #pragma unroll
            for (int j = 0; j < 2; j++) {
                int idx = t + j*256;                 // 512 cp16s
                int ks = idx >> 8, off = idx & 255;
                unsigned d = (unsigned)__cvta_generic_to_shared(
                    as + buf*A_H + (ks*256 + off)*8);
                cp16(d, g_wAh + (size_t)c*8192 + ks*4096 + yblk*2048 + off*8, 16);
            }
        } else if (MODE == 2) {
            #pragma unroll
            for (int j = 0; j < 2; j++) {
                int idx = t + j*256;
                unsigned d = (unsigned)__cvta_generic_to_shared(as + buf*A_H + idx*8);
                cp16(d, g_wth + (size_t)c*4096 + idx*8, 16);
            }
        } else {
            if (t < 128) {
                unsigned d = (unsigned)__cvta_generic_to_shared(as + buf*A_H + t*8);
                cp16(d, g_wMh + (size_t)c*1024 + t*8, 16);
            }
        }
        if (MODE != 2) {
            const __half* srcT = (MODE==0) ? g_xTh : g_xattTh;
            int tap = c >> 2, ci0 = (c & 3) << 5;
            int dy = tap/3 - 1, dxx = tap - (tap/3)*3 - 1;
            int yp = y + dy, xp = bpx + dxx;
            bool valid = ((unsigned)yp < 128u) && ((unsigned)xp < 128u);
            int sz = valid ? 16 : 0;
            const __half* src = srcT + ((size_t)((bI<<14) + (valid ? (yp<<7)+xp : 0)))*CHN + ci0;
            #pragma unroll
            for (int j = 0; j < 2; j++) {
                int seg = kq0 + j*2;                 // 0..3, 16B each
                unsigned d = (unsigned)__cvta_generic_to_shared(
                    bsm + buf*B_H + bpx*40 + seg*8);
                cp16(d, src + seg*8, sz);
            }
        }
    };

    // ==================== MODE 0 / 1: 3-stage pipeline ====================
    if (MODE != 2) {
        stage(0, 0); cp_commit();
        stage(1, 1); cp_commit();
        for (int c = 0; c < 36; c++) {
            if (c < 35) cp_wait1(); else cp_wait0();
            __syncthreads();
            if (c + 2 < 36) { stage(c+2, (c+2)%3); cp_commit(); }
            const uint4*  ab = (const uint4*)(as + (c%3)*A_H);
            const __half* bb = bsm + (c%3)*B_H;
            #pragma unroll
            for (int ks = 0; ks < 2; ks++) {
                uint4 af[MT];
                #pragma unroll
                for (int mt = 0; mt < MT; mt++)
                    af[mt] = ab[((ks*NH + halfsel)*MT + mt)*32 + lane];
                #pragma unroll
                for (int nt = 0; nt < NT; nt++) {
                    const __half* bp = bb + (pxw + nt*8 + g)*40 + ks*16 + tig*2;
                    uint32_t b0 = *(const uint32_t*)bp;
                    uint32_t b1 = *(const uint32_t*)(bp + 8);
                    #pragma unroll
                    for (int mt = 0; mt < MT; mt++)
                        mma_f16(acc[mt][nt], (const uint32_t*)&af[mt], b0, b1);
                }
            }
        }
    }
    // ============ MODE 2: 2-stage + register-pipelined gather =============
    else {
        stage(0, 0); cp_commit();
        {   // gather chunk 0 (tap 0, ci 0..31)
            const __half* xb = g_xattTh + ((size_t)(bI << 14))*CHN + lane;
            const float4* fw0 = (const float4*)cwT;
            const int4*   iw0 = (const int4*)ciT;
            __half* bd = bsm + lane;
            #pragma unroll 4
            for (int idx = 0; idx < 16; idx++) {
                int px = wid + idx*8;
                float4 f = fw0[px]; int4 ix = iw0[px];
                float v = f.x*__half2float(xb[(size_t)ix.x*CHN])
                        + f.y*__half2float(xb[(size_t)ix.y*CHN])
                        + f.z*__half2float(xb[(size_t)ix.z*CHN])
                        + f.w*__half2float(xb[(size_t)ix.w*CHN]);
                bd[px*40] = __float2half(v);
            }
        }
        cp_wait0(); __syncthreads();

        for (int c = 0; c < 36; c++) {
            const int buf = c & 1;
            if (c < 35) { stage(c+1, buf^1); cp_commit(); }

            const __half* xb = nullptr; const float4* fw = nullptr;
            const int4* iwp = nullptr; __half* bdst = nullptr;
            if (c < 35) {
                int cn = c + 1, tapn = cn >> 2, ci0n = (cn & 3) << 5;
                xb   = g_xattTh + ((size_t)(bI << 14))*CHN + ci0n + lane;
                fw   = ((const float4*)cwT) + tapn*128;
                iwp  = ((const int4*)ciT)  + tapn*128;
                bdst = bsm + (buf^1)*B_H + lane;
            }

            const uint4*  ab = (const uint4*)(as + buf*A_H);
            const __half* bb = bsm + buf*B_H;
            #pragma unroll
            for (int ks = 0; ks < 2; ks++) {
                uint4 af[MT];
                #pragma unroll
                for (int mt = 0; mt < MT; mt++)
                    af[mt] = ab[((ks*NH + halfsel)*MT + mt)*32 + lane];
                #pragma unroll
                for (int sub = 0; sub < 2; sub++) {
                    float lv[16]; int pxa[4];
                    if (c < 35) {
                        #pragma unroll
                        for (int q = 0; q < 4; q++) {
                            int px = wid + (ks*8 + sub*4 + q)*8;
                            pxa[q] = px;
                            int4 ix = iwp[px];
                            lv[q*4+0] = __half2float(xb[(size_t)ix.x*CHN]);
                            lv[q*4+1] = __half2float(xb[(size_t)ix.y*CHN]);
                            lv[q*4+2] = __half2float(xb[(size_t)ix.z*CHN]);
                            lv[q*4+3] = __half2float(xb[(size_t)ix.w*CHN]);
                        }
                    }
                    #pragma unroll
                    for (int nt = sub*2; nt < sub*2 + 2; nt++) {
                        const __half* bp = bb + (pxw + nt*8 + g)*40 + ks*16 + tig*2;
                        uint32_t b0 = *(const uint32_t*)bp;
                        uint32_t b1 = *(const uint32_t*)(bp + 8);
                        #pragma unroll
                        for (int mt = 0; mt < MT; mt++)
                            mma_f16(acc[mt][nt], (const uint32_t*)&af[mt], b0, b1);
                    }
                    if (c < 35) {
                        #pragma unroll
                        for (int q = 0; q < 4; q++) {
                            float4 f = fw[pxa[q]];
                            float v = f.x*lv[q*4]   + f.y*lv[q*4+1]
                                    + f.z*lv[q*4+2] + f.w*lv[q*4+3];
                            bdst[pxa[q]*40] = __float2half(v);
                        }
                    }
                }
            }
            if (c < 35) { cp_wait0(); __syncthreads(); }
        }
    }

    // ---- epilogue ----
    const int prem = px0 & (HW-1);
    #pragma unroll
    for (int mt = 0; mt < MT; mt++) {
        #pragma unroll
        for (int r = 0; r < 2; r++) {
            const int coL = cow + mt*16 + r*8 + g;
            const int coG = co0 + coL;
            float bv = 0.f; float* plane = nullptr;
            bool sig = false, dostats = false; int sidx = 0;
            if (MODE == 0) {
                bv = g_biasA[coG];
                if (coG < 128) { plane = g_attn + ((size_t)(bI*CHN + coG) << 14); sig = true; }
                else {
                    plane = g_feat + ((size_t)(bI*CHN + coG - 128) << 14);
                    dostats = true; sidx = (bI*CHN + coG - 128)*2;
                }
            } else if (MODE == 2) {
                bv = g_biasO[coL];
                plane = g_dconv + ((size_t)(bI*CHN + coL) << 14);
                dostats = true; sidx = (BB*CHN + bI*CHN + coL)*2;
            } else {
                bv = g_biasM[coL];
                if (coL < 27) { plane = g_off + ((size_t)(bI*27 + coL) << 14); sig = (coL >= 18); }
            }
            float s = 0.f, q = 0.f;
            #pragma unroll
            for (int nt = 0; nt < NT; nt++) {
                float v0 = acc[mt][nt][r*2]   + bv;
                float v1 = acc[mt][nt][r*2+1] + bv;
                if (sig) { v0 = sigmoidf(v0); v1 = sigmoidf(v1); }
                int col = pxw + nt*8 + 2*tig;
                if (plane) *(float2*)&plane[prem + col] = make_float2(v0, v1);
                s += v0 + v1; q += v0*v0 + v1*v1;
            }
            if (dostats) {
                s += __shfl_xor_sync(0xffffffffu, s, 1);
                s += __shfl_xor_sync(0xffffffffu, s, 2);
                q += __shfl_xor_sync(0xffffffffu, q, 1);
                q += __shfl_xor_sync(0xffffffffu, q, 2);
                if (tig == 0) {
                    atomicAdd(&g_stats[sidx],   s);
                    atomicAdd(&g_stats[sidx+1], q);
                }
            }
        }
    }
}

__global__ void finalize_stats_k() {
    int i = blockIdx.x*blockDim.x + threadIdx.x;
    if (i >= 2*BB*CHN) return;
    float s = g_stats[2*i], q = g_stats[2*i+1];
    float mu  = s * (1.0f/HW);
    float var = q * (1.0f/HW) - mu*mu;
    g_norm[2*i]   = mu;
    g_norm[2*i+1] = rsqrtf(var + 1e-5f);
}

// ---- x_attned = lrelu(IN(feat)) * attn ; NCHW fp32 + NHWC fp16 ----
__global__ __launch_bounds__(256) void xatt_k() {
    __shared__ float s[32][133];
    int bid = blockIdx.x;
    int pg = bid & 127, cg = (bid >> 7) & 3, b = bid >> 9;
    int t = threadIdx.x;
    int px0 = pg << 7;
    #pragma unroll
    for (int j = 0; j < 16; j++) {
        int idx = t + j*256;
        int ch = idx >> 7, px = idx & 127;
        int plane = b*CHN + (cg<<5) + ch;
        size_t gi = ((size_t)plane << 14) + px0 + px;
        float mu = g_norm[2*plane], rs = g_norm[2*plane+1];
        float v = (g_feat[gi] - mu)*rs;
        v = v > 0.f ? v : 0.2f*v;
        float o = v * g_attn[gi];
        g_xatt[gi] = o;
        s[ch][px] = o;
    }
    __syncthreads();
    #pragma unroll
    for (int j = 0; j < 16; j++) {
        int idx = t + j*256;
        int px = idx >> 5, ch = idx & 31;
        g_xattTh[((size_t)((b<<14) + px0 + px))*CHN + (cg<<5) + ch] =
            __float2half(s[ch][px]);
    }
}

// ---- final: out = xatt + lrelu(IN(dconv)) * (1 - attn) ----
__global__ void final_k(float* __restrict__ out) {
    int i = blockIdx.x*256 + threadIdx.x;
    int plane = i >> 12;
    float mu = g_norm[2*(BB*CHN + plane)], rs = g_norm[2*(BB*CHN + plane)+1];
    float4 d  = ((const float4*)g_dconv)[i];
    float4 a  = ((const float4*)g_attn)[i];
    float4 xa = ((const float4*)g_xatt)[i];
    float4 o; float v;
    v = (d.x - mu)*rs; v = v > 0.f ? v : 0.2f*v; o.x = xa.x + v*(1.f - a.x);
    v = (d.y - mu)*rs; v = v > 0.f ? v : 0.2f*v; o.y = xa.y + v*(1.f - a.y);
    v = (d.z - mu)*rs; v = v > 0.f ? v : 0.2f*v; o.z = xa.z + v*(1.f - a.z);
    v = (d.w - mu)*rs; v = v > 0.f ? v : 0.2f*v; o.w = xa.w + v*(1.f - a.w);
    ((float4*)out)[i] = o;
}

// ---------------- launch ----------------
extern "C" void kernel_launch(void* const* d_in, const int* in_sizes, int n_in,
                              void* d_out, int out_size) {
    const float* x      = (const float*)d_in[0];
    const float* w_attn = (const float*)d_in[1];
    const float* b_attn = (const float*)d_in[2];
    const float* w_feat = (const float*)d_in[3];
    const float* b_feat = (const float*)d_in[4];
    const float* w_org  = (const float*)d_in[5];
    const float* b_org  = (const float*)d_in[6];
    const float* w_off  = (const float*)d_in[7];
    const float* b_off  = (const float*)d_in[8];
    const float* w_mask = (const float*)d_in[9];
    const float* b_mask = (const float*)d_in[10];
    float* out = (float*)d_out;

    const int SM_M0 = 3*(4096 + 5120)*2;                     // 55296
    const int SM_M1 = 3*(1024 + 5120)*2;                     // 36864
    const int SM_M2 = 2*(4096 + 5120)*2 + 4608*4 + 4608*4;   // 73728
    cudaFuncSetAttribute(gemm_k<0>, cudaFuncAttributeMaxDynamicSharedMemorySize, SM_M0);
    cudaFuncSetAttribute(gemm_k<1>, cudaFuncAttributeMaxDynamicSharedMemorySize, SM_M1);
    cudaFuncSetAttribute(gemm_k<2>, cudaFuncAttributeMaxDynamicSharedMemorySize, SM_M2);

    prep_k<<<1152, 256>>>(w_attn, w_feat, w_org, w_off, w_mask,
                          b_attn, b_feat, b_org, b_off, b_mask);
    transpose_k<<<2048, 256>>>(x);
    gemm_k<0><<<dim3(512, 2), 256, SM_M0>>>();     // attn + feat conv
    finalize_stats_k<<<4, 256>>>();
    xatt_k<<<2048, 256>>>();
    gemm_k<1><<<512, 256, SM_M1>>>();              // offset + mask conv
    gemm_k<2><<<512, 256, SM_M2>>>();              // fused gather + deform einsum
    finalize_stats_k<<<4, 256>>>();
    final_k<<<8192, 256>>>(out);
}

// round 11
// speedup vs baseline: 1.4756x; 1.0656x over previous
#include <cuda_runtime.h>
#include <cuda_fp16.h>
#include <cstdint>

#define BB  4
#define CHN 128
#define HH  128
#define WW  128
#define HW  16384
#define K2C 1152
#define NPX (BB*HW)
#define NC  18                      // 64-k chunks

// ---------------- scratch (device globals; allocation-free) ----------------
__device__ __half g_xTh   [(size_t)NPX*CHN];   // x in NHWC, fp16
__device__ __half g_xattTh[(size_t)NPX*CHN];   // x_attned in NHWC, fp16
__device__ float g_attn [(size_t)BB*CHN*HW];   // sigmoid(conv_attn), NCHW
__device__ float g_feat [(size_t)BB*CHN*HW];   // raw conv_feat, NCHW
__device__ float g_xatt [(size_t)BB*CHN*HW];   // x_attned, NCHW
__device__ float g_off  [(size_t)BB*27*HW];    // 18 offsets + 9 sigmoided masks
__device__ float g_dconv[(size_t)BB*CHN*HW];   // deform conv output
// fp16 fragment-packed weights (m16n8k16 layout), indexed by 32-k chunks
__device__ __half g_wAh[36*2*4*4*32*8];        // [c32][ks2][hb4][mt4][lane][8] attn+feat
__device__ __half g_wth[36*2*2*4*32*8];        // [c32][ks2][hb2][mt4][lane][8] w_org
__device__ __half g_wMh[36*2*2*32*8];          // [c32][ks2][mt2][lane][8]      off/mask
__device__ float g_biasA[256];
__device__ float g_biasM[32];
__device__ float g_biasO[128];
__device__ float g_stats[2*BB*CHN*2];

__device__ __forceinline__ float sigmoidf(float v) { return 1.0f/(1.0f + __expf(-v)); }

__device__ __forceinline__ void mma_f16(float* d, const uint32_t* a,
                                        uint32_t b0, uint32_t b1) {
    asm volatile(
        "mma.sync.aligned.m16n8k16.row.col.f32.f16.f16.f32 "
        "{%0,%1,%2,%3},{%4,%5,%6,%7},{%8,%9},{%0,%1,%2,%3};\n"
        : "+f"(d[0]), "+f"(d[1]), "+f"(d[2]), "+f"(d[3])
        : "r"(a[0]), "r"(a[1]), "r"(a[2]), "r"(a[3]), "r"(b0), "r"(b1));
}

__device__ __forceinline__ void cp16(unsigned dst, const void* src, int srcsize) {
    asm volatile("cp.async.cg.shared.global [%0], [%1], 16, %2;\n"
                 :: "r"(dst), "l"(src), "r"(srcsize));
}
__device__ __forceinline__ void cp_commit() { asm volatile("cp.async.commit_group;\n"); }
__device__ __forceinline__ void cp_wait0()  { asm volatile("cp.async.wait_group 0;\n"); }
__device__ __forceinline__ void cp_wait1()  { asm volatile("cp.async.wait_group 1;\n"); }

// ---------------- prep: pack weights into fp16 fragments ----------------
__global__ void prep_k(const float* __restrict__ w_attn, const float* __restrict__ w_feat,
                       const float* __restrict__ w_org,  const float* __restrict__ w_off,
                       const float* __restrict__ w_mask,
                       const float* __restrict__ b_attn, const float* __restrict__ b_feat,
                       const float* __restrict__ b_org,  const float* __restrict__ b_off,
                       const float* __restrict__ b_mask)
{
    int i = blockIdx.x*256 + threadIdx.x;       // 0 .. 294911
    {   // g_wAh
        int e = i & 7, lane = (i>>3) & 31, mt = (i>>8) & 3,
            hb = (i>>10) & 3, ks = (i>>12) & 1, c = i >> 13;
        int g = lane>>2, tig = lane&3, r = e>>1, h = e&1;
        int co = hb*64 + mt*16 + g + ((r&1) ? 8 : 0);
        int k  = c*32 + ks*16 + tig*2 + h + ((r&2) ? 8 : 0);
        int tap = k >> 7, ci = k & 127;
        float v = (co < 128) ? w_attn[(co*128+ci)*9 + tap]
                             : w_feat[((co-128)*128+ci)*9 + tap];
        g_wAh[i] = __float2half(v);
    }
    if (i < 36*2*2*4*32*8) {   // g_wth
        int e = i & 7, lane = (i>>3) & 31, mt = (i>>8) & 3,
            hb = (i>>10) & 1, ks = (i>>11) & 1, c = i >> 12;
        int g = lane>>2, tig = lane&3, r = e>>1, h = e&1;
        int co = hb*64 + mt*16 + g + ((r&1) ? 8 : 0);
        int k  = c*32 + ks*16 + tig*2 + h + ((r&2) ? 8 : 0);
        int tap = k >> 7, ci = k & 127;
        g_wth[i] = __float2half(w_org[(co*128+ci)*9 + tap]);
    }
    if (i < 36*2*2*32*8) {     // g_wMh
        int e = i & 7, lane = (i>>3) & 31, mt = (i>>8) & 1,
            ks = (i>>9) & 1, c = i >> 10;
        int g = lane>>2, tig = lane&3, r = e>>1, h = e&1;
        int co = mt*16 + g + ((r&1) ? 8 : 0);
        int k  = c*32 + ks*16 + tig*2 + h + ((r&2) ? 8 : 0);
        int tap = k >> 7, ci = k & 127;
        float v = 0.f;
        if (co < 18)      v = w_off [(co*128+ci)*9 + tap];
        else if (co < 27) v = w_mask[((co-18)*128+ci)*9 + tap];
        g_wMh[i] = __float2half(v);
    }
    if (i < 256) g_biasA[i] = (i < 128) ? b_attn[i] : b_feat[i-128];
    if (i < 128) g_biasO[i] = b_org[i];
    if (i < 32)  g_biasM[i] = (i < 18) ? b_off[i] : (i < 27 ? b_mask[i-18] : 0.f);
    if (i < 2*BB*CHN*2) g_stats[i] = 0.f;
}

// ---------------- NCHW -> NHWC(fp16) transpose of x ----------------
__global__ __launch_bounds__(256) void transpose_k(const float* __restrict__ x) {
    __shared__ float s[32][133];
    int bid = blockIdx.x;
    int pg = bid & 127, cg = (bid >> 7) & 3, b = bid >> 9;
    int t = threadIdx.x;
    int px0 = pg << 7;
    #pragma unroll
    for (int j = 0; j < 16; j++) {
        int idx = t + j*256;
        int ch = idx >> 7, px = idx & 127;
        s[ch][px] = x[((size_t)(b*CHN + (cg<<5) + ch) << 14) + px0 + px];
    }
    __syncthreads();
    #pragma unroll
    for (int j = 0; j < 16; j++) {
        int idx = t + j*256;
        int px = idx >> 5, ch = idx & 31;
        g_xTh[((size_t)((b<<14) + px0 + px))*CHN + (cg<<5) + ch] = __float2half(s[ch][px]);
    }
}

// ---------------- generic fp16 GEMM, 64-k chunks -------------------------
// MODE 0: attn+feat conv; MODE 1: off/mask conv; MODE 2: fused deform einsum
template<int MODE>
__global__ __launch_bounds__(256, 2) void gemm_k()
{
    constexpr int MT     = (MODE==1) ? 2 : 4;
    constexpr int NT     = (MODE==1) ? 2 : 4;
    constexpr int NH     = (MODE==1) ? 1 : 2;
    constexpr int A_H    = (MODE==1) ? 2048 : 8192;   // halves per stage
    constexpr int B_H    = 128*72;                    // 9216 halves per stage
    constexpr int STAGES = (MODE==2) ? 2 : 3;
    extern __shared__ __half smh[];
    __half* as  = smh;
    __half* bsm = smh + STAGES*A_H;
    float*  cwT = (float*)(smh + STAGES*(A_H + B_H));  // MODE2 only
    int*    ciT = (int*)(cwT + 4608);

    const int t = threadIdx.x;
    const int wid = t >> 5, lane = t & 31, g = lane >> 2, tig = lane & 3;
    const int px0 = blockIdx.x << 7;
    const int bI = px0 >> 14, y = (px0 >> 7) & 127;
    const int yblk = (MODE==0) ? blockIdx.y : 0;
    const int co0 = yblk << 7;
    const int halfsel = (MODE==1) ? 0 : (wid >> 2);
    const int cow = halfsel * 64;
    const int pxw = (MODE==1) ? (wid << 4) : ((wid & 3) << 5);

    float acc[MT][NT][4];
    #pragma unroll
    for (int mt = 0; mt < MT; mt++)
        #pragma unroll
        for (int nt = 0; nt < NT; nt++)
            #pragma unroll
            for (int j = 0; j < 4; j++) acc[mt][nt][j] = 0.f;

    // ---- MODE 2: precompute bilinear corner tables ----
    if (MODE == 2) {
        const float* ob = g_off + (((size_t)bI*27) << 14) + y*WW;
        for (int pt = t; pt < 1152; pt += 256) {
            int tap = pt >> 7, px = pt & 127;
            float dy = ob[((size_t)(2*tap  ) << 14) + px];
            float dx = ob[((size_t)(2*tap+1) << 14) + px];
            float mk = ob[((size_t)(18+tap ) << 14) + px];
            float yy = dy + (float)(y  + tap/3 - 1);
            float xx = dx + (float)(px + tap%3 - 1);
            float y0f = floorf(yy), x0f = floorf(xx);
            float wy = yy - y0f, wx = xx - x0f;
            int y0 = (int)y0f, x0 = (int)x0f;
            float fw[4]; int fi[4];
            #pragma unroll
            for (int cnr = 0; cnr < 4; cnr++) {
                int ddy = cnr >> 1, ddx = cnr & 1;
                int yi = y0 + ddy, xi = x0 + ddx;
                bool valid = ((unsigned)yi < (unsigned)HH) && ((unsigned)xi < (unsigned)WW);
                int yc = min(max(yi, 0), HH-1);
                int xc = min(max(xi, 0), WW-1);
                float wgt = (ddy ? wy : 1.f - wy) * (ddx ? wx : 1.f - wx) * mk;
                fw[cnr] = valid ? wgt : 0.f;
                fi[cnr] = yc*WW + xc;
            }
            ((float4*)cwT)[pt] = make_float4(fw[0], fw[1], fw[2], fw[3]);
            ((int4*)ciT)[pt]   = make_int4(fi[0], fi[1], fi[2], fi[3]);
        }
        __syncthreads();
    }

    // ---- staging helper (caller commits); c = 64-k chunk index ----
    auto stage = [&](int c, int buf) {
        if (MODE == 0) {
            #pragma unroll
            for (int j = 0; j < 4; j++) {
                int idx = t + j*256;                 // 1024 cp16s
                int sub = idx >> 9, oks = (idx >> 8) & 1, off = idx & 255;
                unsigned d = (unsigned)__cvta_generic_to_shared(as + buf*A_H + idx*8);
                cp16(d, g_wAh + (size_t)(2*c+sub)*8192 + oks*4096 + yblk*2048 + off*8, 16);
            }
        } else if (MODE == 2) {
            #pragma unroll
            for (int j = 0; j < 4; j++) {
                int idx = t + j*256;
                int sub = idx >> 9, rest = idx & 511;
                unsigned d = (unsigned)__cvta_generic_to_shared(as + buf*A_H + idx*8);
                cp16(d, g_wth + (size_t)(2*c+sub)*4096 + rest*8, 16);
            }
        } else {
            int sub = t >> 7, rest = t & 127;
            unsigned d = (unsigned)__cvta_generic_to_shared(as + buf*A_H + t*8);
            cp16(d, g_wMh + (size_t)(2*c+sub)*1024 + rest*8, 16);
        }
        if (MODE != 2) {
            const __half* srcT = (MODE==0) ? g_xTh : g_xattTh;
            int tap = c >> 1, ci0 = (c & 1) << 6;
            int dy = tap/3 - 1, dxx = tap - (tap/3)*3 - 1;
            int row = t >> 1;
            int yp = y + dy, xp = row + dxx;
            bool valid = ((unsigned)yp < 128u) && ((unsigned)xp < 128u);
            int sz = valid ? 16 : 0;
            const __half* src = srcT + ((size_t)((bI<<14) + (valid ? (yp<<7)+xp : 0)))*CHN + ci0;
            #pragma unroll
            for (int j = 0; j < 4; j++) {
                int seg = (t & 1)*4 + j;             // 0..7, 16B each
                unsigned d = (unsigned)__cvta_generic_to_shared(
                    bsm + buf*B_H + row*72 + seg*8);
                cp16(d, src + seg*8, sz);
            }
        }
    };

    // ==================== MODE 0 / 1: 3-stage pipeline ====================
    if (MODE != 2) {
        stage(0, 0); cp_commit();
        stage(1, 1); cp_commit();
        for (int c = 0; c < NC; c++) {
            if (c < NC-1) cp_wait1(); else cp_wait0();
            __syncthreads();
            if (c + 2 < NC) { stage(c+2, (c+2)%3); cp_commit(); }
            const uint4*  ab = (const uint4*)(as + (c%3)*A_H);
            const __half* bb = bsm + (c%3)*B_H;
            #pragma unroll
            for (int s = 0; s < 4; s++) {
                uint4 af[MT];
                #pragma unroll
                for (int mt = 0; mt < MT; mt++)
                    af[mt] = ab[(s*NH + halfsel)*MT*32 + mt*32 + lane];
                #pragma unroll
                for (int nt = 0; nt < NT; nt++) {
                    const __half* bp = bb + (pxw + nt*8 + g)*72 + s*16 + tig*2;
                    uint32_t b0 = *(const uint32_t*)bp;
                    uint32_t b1 = *(const uint32_t*)(bp + 8);
                    #pragma unroll
                    for (int mt = 0; mt < MT; mt++)
                        mma_f16(acc[mt][nt], (const uint32_t*)&af[mt], b0, b1);
                }
            }
        }
    }
    // ============ MODE 2: 2-stage + register-pipelined gather =============
    else {
        stage(0, 0); cp_commit();
        {   // gather chunk 0 (tap 0, ci 0..63)
            const float4* fw0 = (const float4*)cwT;
            const int4*   iw0 = (const int4*)ciT;
            #pragma unroll
            for (int h = 0; h < 2; h++) {
                const __half* xb = g_xattTh + ((size_t)(bI << 14))*CHN + h*32 + lane;
                __half* bd = bsm + h*32 + lane;
                #pragma unroll 4
                for (int idx = 0; idx < 16; idx++) {
                    int px = wid + idx*8;
                    float4 f = fw0[px]; int4 ix = iw0[px];
                    float v = f.x*__half2float(xb[(size_t)ix.x*CHN])
                            + f.y*__half2float(xb[(size_t)ix.y*CHN])
                            + f.z*__half2float(xb[(size_t)ix.z*CHN])
                            + f.w*__half2float(xb[(size_t)ix.w*CHN]);
                    bd[px*72] = __float2half(v);
                }
            }
        }
        cp_wait0(); __syncthreads();

        for (int c = 0; c < NC; c++) {
            const int buf = c & 1;
            if (c < NC-1) { stage(c+1, buf^1); cp_commit(); }

            const __half* xbb = nullptr; const float4* fw = nullptr;
            const int4* iwp = nullptr; __half* bdb = nullptr;
            if (c < NC-1) {
                int cn = c + 1, tapn = cn >> 1, cib = (cn & 1) << 6;
                xbb = g_xattTh + ((size_t)(bI << 14))*CHN + cib + lane;
                fw  = ((const float4*)cwT) + tapn*128;
                iwp = ((const int4*)ciT)  + tapn*128;
                bdb = bsm + (buf^1)*B_H + lane;
            }

            const uint4*  ab = (const uint4*)(as + buf*A_H);
            const __half* bb = bsm + buf*B_H;
            #pragma unroll
            for (int s = 0; s < 4; s++) {
                uint4 af[MT];
                #pragma unroll
                for (int mt = 0; mt < MT; mt++)
                    af[mt] = ab[(s*2 + halfsel)*128 + mt*32 + lane];
                #pragma unroll
                for (int sub = 0; sub < 2; sub++) {
                    const int sl = s*2 + sub;            // 0..7
                    const int hh = sl >> 2, qb = sl & 3;
                    float lv[16]; int pxa[4];
                    if (c < NC-1) {
                        const __half* xb = xbb + hh*32;
                        #pragma unroll
                        for (int q = 0; q < 4; q++) {
                            int px = wid + (qb*4 + q)*8;
                            pxa[q] = px;
                            int4 ix = iwp[px];
                            lv[q*4+0] = __half2float(xb[(size_t)ix.x*CHN]);
                            lv[q*4+1] = __half2float(xb[(size_t)ix.y*CHN]);
                            lv[q*4+2] = __half2float(xb[(size_t)ix.z*CHN]);
                            lv[q*4+3] = __half2float(xb[(size_t)ix.w*CHN]);
                        }
                    }
                    #pragma unroll
                    for (int nt = sub*2; nt < sub*2 + 2; nt++) {
                        const __half* bp = bb + (pxw + nt*8 + g)*72 + s*16 + tig*2;
                        uint32_t b0 = *(const uint32_t*)bp;
                        uint32_t b1 = *(const uint32_t*)(bp + 8);
                        #pragma unroll
                        for (int mt = 0; mt < MT; mt++)
                            mma_f16(acc[mt][nt], (const uint32_t*)&af[mt], b0, b1);
                    }
                    if (c < NC-1) {
                        __half* bd = bdb + hh*32;
                        #pragma unroll
                        for (int q = 0; q < 4; q++) {
                            float4 f = fw[pxa[q]];
                            float v = f.x*lv[q*4]   + f.y*lv[q*4+1]
                                    + f.z*lv[q*4+2] + f.w*lv[q*4+3];
                            bd[pxa[q]*72] = __float2half(v);
                        }
                    }
                }
            }
            if (c < NC-1) { cp_wait0(); __syncthreads(); }
        }
    }

    // ---- epilogue ----
    const int prem = px0 & (HW-1);
    #pragma unroll
    for (int mt = 0; mt < MT; mt++) {
        #pragma unroll
        for (int r = 0; r < 2; r++) {
            const int coL = cow + mt*16 + r*8 + g;
            const int coG = co0 + coL;
            float bv = 0.f; float* plane = nullptr;
            bool sig = false, dostats = false; int sidx = 0;
            if (MODE == 0) {
                bv = g_biasA[coG];
                if (coG < 128) { plane = g_attn + ((size_t)(bI*CHN + coG) << 14); sig = true; }
                else {
                    plane = g_feat + ((size_t)(bI*CHN + coG - 128) << 14);
                    dostats = true; sidx = (bI*CHN + coG - 128)*2;
                }
            } else if (MODE == 2) {
                bv = g_biasO[coL];
                plane = g_dconv + ((size_t)(bI*CHN + coL) << 14);
                dostats = true; sidx = (BB*CHN + bI*CHN + coL)*2;
            } else {
                bv = g_biasM[coL];
                if (coL < 27) { plane = g_off + ((size_t)(bI*27 + coL) << 14); sig = (coL >= 18); }
            }
            float s = 0.f, q = 0.f;
            #pragma unroll
            for (int nt = 0; nt < NT; nt++) {
                float v0 = acc[mt][nt][r*2]   + bv;
                float v1 = acc[mt][nt][r*2+1] + bv;
                if (sig) { v0 = sigmoidf(v0); v1 = sigmoidf(v1); }
                int col = pxw + nt*8 + 2*tig;
                if (plane) *(float2*)&plane[prem + col] = make_float2(v0, v1);
                s += v0 + v1; q += v0*v0 + v1*v1;
            }
            if (dostats) {
                s += __shfl_xor_sync(0xffffffffu, s, 1);
                s += __shfl_xor_sync(0xffffffffu, s, 2);
                q += __shfl_xor_sync(0xffffffffu, q, 1);
                q += __shfl_xor_sync(0xffffffffu, q, 2);
                if (tig == 0) {
                    atomicAdd(&g_stats[sidx],   s);
                    atomicAdd(&g_stats[sidx+1], q);
                }
            }
        }
    }
}

// ---- x_attned = lrelu(IN(feat)) * attn ; NCHW fp32 + NHWC fp16 ----
__global__ __launch_bounds__(256) void xatt_k() {
    __shared__ float s[32][133];
    int bid = blockIdx.x;
    int pg = bid & 127, cg = (bid >> 7) & 3, b = bid >> 9;
    int t = threadIdx.x;
    int px0 = pg << 7;
    #pragma unroll
    for (int j = 0; j < 16; j++) {
        int idx = t + j*256;
        int ch = idx >> 7, px = idx & 127;
        int plane = b*CHN + (cg<<5) + ch;
        size_t gi = ((size_t)plane << 14) + px0 + px;
        float su = g_stats[2*plane], sq = g_stats[2*plane+1];
        float mu = su * (1.0f/HW);
        float rs = rsqrtf(sq * (1.0f/HW) - mu*mu + 1e-5f);
        float v = (g_feat[gi] - mu)*rs;
        v = v > 0.f ? v : 0.2f*v;
        float o = v * g_attn[gi];
        g_xatt[gi] = o;
        s[ch][px] = o;
    }
    __syncthreads();
    #pragma unroll
    for (int j = 0; j < 16; j++) {
        int idx = t + j*256;
        int px = idx >> 5, ch = idx & 31;
        g_xattTh[((size_t)((b<<14) + px0 + px))*CHN + (cg<<5) + ch] =
            __float2half(s[ch][px]);
    }
}

// ---- final: out = xatt + lrelu(IN(dconv)) * (1 - attn) ----
__global__ void final_k(float* __restrict__ out) {
    int i = blockIdx.x*256 + threadIdx.x;
    int plane = i >> 12;
    float su = g_stats[2*(BB*CHN + plane)], sq = g_stats[2*(BB*CHN + plane)+1];
    float mu = su * (1.0f/HW);
    float rs = rsqrtf(sq * (1.0f/HW) - mu*mu + 1e-5f);
    float4 d  = ((const float4*)g_dconv)[i];
    float4 a  = ((const float4*)g_attn)[i];
    float4 xa = ((const float4*)g_xatt)[i];
    float4 o; float v;
    v = (d.x - mu)*rs; v = v > 0.f ? v : 0.2f*v; o.x = xa.x + v*(1.f - a.x);
    v = (d.y - mu)*rs; v = v > 0.f ? v : 0.2f*v; o.y = xa.y + v*(1.f - a.y);
    v = (d.z - mu)*rs; v = v > 0.f ? v : 0.2f*v; o.z = xa.z + v*(1.f - a.z);
    v = (d.w - mu)*rs; v = v > 0.f ? v : 0.2f*v; o.w = xa.w + v*(1.f - a.w);
    ((float4*)out)[i] = o;
}

// ---------------- launch ----------------
extern "C" void kernel_launch(void* const* d_in, const int* in_sizes, int n_in,
                              void* d_out, int out_size) {
    const float* x      = (const float*)d_in[0];
    const float* w_attn = (const float*)d_in[1];
    const float* b_attn = (const float*)d_in[2];
    const float* w_feat = (const float*)d_in[3];
    const float* b_feat = (const float*)d_in[4];
    const float* w_org  = (const float*)d_in[5];
    const float* b_org  = (const float*)d_in[6];
    const float* w_off  = (const float*)d_in[7];
    const float* b_off  = (const float*)d_in[8];
    const float* w_mask = (const float*)d_in[9];
    const float* b_mask = (const float*)d_in[10];
    float* out = (float*)d_out;

    const int SM_M0 = 3*(8192 + 9216)*2;                     // 104448
    const int SM_M1 = 3*(2048 + 9216)*2;                     // 67584
    const int SM_M2 = 2*(8192 + 9216)*2 + 4608*4 + 4608*4;   // 106496
    cudaFuncSetAttribute(gemm_k<0>, cudaFuncAttributeMaxDynamicSharedMemorySize, SM_M0);
    cudaFuncSetAttribute(gemm_k<1>, cudaFuncAttributeMaxDynamicSharedMemorySize, SM_M1);
    cudaFuncSetAttribute(gemm_k<2>, cudaFuncAttributeMaxDynamicSharedMemorySize, SM_M2);

    prep_k<<<1152, 256>>>(w_attn, w_feat, w_org, w_off, w_mask,
                          b_attn, b_feat, b_org, b_off, b_mask);
    transpose_k<<<2048, 256>>>(x);
    gemm_k<0><<<dim3(512, 2), 256, SM_M0>>>();     // attn + feat conv
    xatt_k<<<2048, 256>>>();
    gemm_k<1><<<512, 256, SM_M1>>>();              // offset + mask conv
    gemm_k<2><<<512, 256, SM_M2>>>();              // fused gather + deform einsum
    final_k<<<8192, 256>>>(out);
}